// round 5
// baseline (speedup 1.0000x reference)
#include <cuda_runtime.h>
#include <cuda_bf16.h>

// AGNNConv:
//   Xp = X @ W;  attn[e] = dot(Xp[row[e]], Xp[col[e]]) * w
//   out[i] = sum_{e: row[e]==i} attn[e] * Xp[col[e]]
// Inputs: X [N*64 f32], W [64*64 f32], attention_w [1 f32],
//         row [E i32 sorted], col [E i32].  Output: out [N*64 f32]

#define D 64
#define MAX_NODES 50000
#define EPG 8               // edges per 8-lane group
#define EPW (4 * EPG)       // edges per warp
#define RPB 128             // rows per block (gemm)
#define XS_STRIDE 76        // 76*4=304B: rows land 16 banks apart (2-way max)

__device__ float4 g_Xp4[MAX_NODES * (D / 4)];

// ---------------------------------------------------------------------------
// Kernel 1: Xp = X @ W + zero out.  256 threads, 128 rows/block.
// Thread (rg=t>>3, dg=t&7): rows [4rg,4rg+4) x cols [8dg,8dg+8).
// Per 4 k-steps: 4 LDS.128 (X rows) + 8 LDS.128 (W) -> 128 FFMA.
// ---------------------------------------------------------------------------
__global__ void __launch_bounds__(256)
gemm_zero_kernel(const float4* __restrict__ X4, const float4* __restrict__ W4,
                 float4* __restrict__ out4, int n_nodes)
{
    __shared__ float Ws[D * D];                 // [k][d], 16 KB
    __shared__ float Xs[RPB * XS_STRIDE];       // 38.9 KB

    int t  = threadIdx.x;
    int r0 = blockIdx.x * RPB;

    float4* Ws4v = reinterpret_cast<float4*>(Ws);
    #pragma unroll
    for (int i = 0; i < 4; ++i) Ws4v[t + 256 * i] = W4[t + 256 * i];

    #pragma unroll
    for (int i = 0; i < 8; ++i) {
        int idx4 = t + 256 * i;
        int r  = idx4 >> 4;
        int k4 = idx4 & 15;
        float4 v = (r0 + r < n_nodes) ? X4[(r0 + r) * 16 + k4]
                                      : make_float4(0.f, 0.f, 0.f, 0.f);
        *reinterpret_cast<float4*>(&Xs[r * XS_STRIDE + k4 * 4]) = v;
    }
    __syncthreads();

    int rg = t >> 3;
    int dg = t & 7;

    float acc[4][8];
    #pragma unroll
    for (int i = 0; i < 4; ++i)
        #pragma unroll
        for (int j = 0; j < 8; ++j) acc[i][j] = 0.f;

    const float* xbase = &Xs[(rg * 4) * XS_STRIDE];
    const float4* Wq = reinterpret_cast<const float4*>(Ws) + dg * 2;

    #pragma unroll 4
    for (int k4 = 0; k4 < 16; ++k4) {
        float4 xv[4];
        #pragma unroll
        for (int i = 0; i < 4; ++i)
            xv[i] = *reinterpret_cast<const float4*>(
                        &xbase[i * XS_STRIDE + k4 * 4]);

        #pragma unroll
        for (int kk = 0; kk < 4; ++kk) {
            int k = k4 * 4 + kk;
            float4 w0 = Wq[k * 16];
            float4 w1 = Wq[k * 16 + 1];
            #pragma unroll
            for (int i = 0; i < 4; ++i) {
                float x = reinterpret_cast<const float*>(&xv[i])[kk];
                acc[i][0] = fmaf(x, w0.x, acc[i][0]);
                acc[i][1] = fmaf(x, w0.y, acc[i][1]);
                acc[i][2] = fmaf(x, w0.z, acc[i][2]);
                acc[i][3] = fmaf(x, w0.w, acc[i][3]);
                acc[i][4] = fmaf(x, w1.x, acc[i][4]);
                acc[i][5] = fmaf(x, w1.y, acc[i][5]);
                acc[i][6] = fmaf(x, w1.z, acc[i][6]);
                acc[i][7] = fmaf(x, w1.w, acc[i][7]);
            }
        }
    }

    float4 z = make_float4(0.f, 0.f, 0.f, 0.f);
    #pragma unroll
    for (int i = 0; i < 4; ++i) {
        int r = r0 + rg * 4 + i;
        if (r < n_nodes) {
            int base = r * 16 + dg * 2;
            g_Xp4[base]     = make_float4(acc[i][0], acc[i][1], acc[i][2], acc[i][3]);
            g_Xp4[base + 1] = make_float4(acc[i][4], acc[i][5], acc[i][6], acc[i][7]);
            out4[base]      = z;
            out4[base + 1]  = z;
        }
    }
}

// ---------------------------------------------------------------------------
// Kernel 2: edge SDDMM + register SpMM scatter, 8 lanes/edge, EPG=8,
// 1-deep software pipeline: next edge's (row,col,xc) loads issue before the
// current edge's shfl-reduce chain, overlapping L2 latency with the reduce.
// ---------------------------------------------------------------------------
__global__ void __launch_bounds__(256)
edge_kernel(const int* __restrict__ row, const int* __restrict__ col,
            const float* __restrict__ attn_w, float4* __restrict__ out4,
            int n_edges)
{
    int warp_id = (blockIdx.x * blockDim.x + threadIdx.x) >> 5;
    int lane    = threadIdx.x & 31;
    int q       = lane & 7;

    int wbase = warp_id * EPW;
    if (wbase >= n_edges) return;

    int e0 = wbase + (lane >> 3) * EPG;
    bool any  = e0 < n_edges;
    int e_end = any ? min(e0 + EPG, n_edges) : 0;
    int e_safe = any ? e0 : 0;

    const float w = __ldg(attn_w);

    // pipeline state for edge i
    int r_cur = row[e_safe];
    int c_cur = col[e_safe];
    float4 xc0 = g_Xp4[c_cur * 16 + q];
    float4 xc1 = g_Xp4[c_cur * 16 + 8 + q];

    int seg_r = r_cur;
    float4 xr0 = g_Xp4[seg_r * 16 + q];
    float4 xr1 = g_Xp4[seg_r * 16 + 8 + q];

    float4 acc0 = make_float4(0.f, 0.f, 0.f, 0.f);
    float4 acc1 = make_float4(0.f, 0.f, 0.f, 0.f);

    #pragma unroll
    for (int i = 0; i < EPG; ++i) {
        // ---- prefetch edge i+1 (issues before the shfl chain below) ----
        int e_n = e0 + i + 1;
        int en_safe = (any && e_n < e_end) ? e_n : e_safe;
        int r_n = row[en_safe];
        int c_n = col[en_safe];
        float4 nxc0 = g_Xp4[c_n * 16 + q];
        float4 nxc1 = g_Xp4[c_n * 16 + 8 + q];

        bool valid = any && (e0 + i < e_end);

        // ---- segment flush ----
        if (valid && r_cur != seg_r) {
            atomicAdd(&out4[seg_r * 16 + q],     acc0);
            atomicAdd(&out4[seg_r * 16 + 8 + q], acc1);
            acc0 = make_float4(0.f, 0.f, 0.f, 0.f);
            acc1 = make_float4(0.f, 0.f, 0.f, 0.f);
            seg_r = r_cur;
            xr0 = g_Xp4[seg_r * 16 + q];
            xr1 = g_Xp4[seg_r * 16 + 8 + q];
        }

        // ---- SDDMM dot + 8-lane all-reduce (3 shfl serve all 4 groups) ----
        float p = xc0.x * xr0.x + xc0.y * xr0.y + xc0.z * xr0.z + xc0.w * xr0.w
                + xc1.x * xr1.x + xc1.y * xr1.y + xc1.z * xr1.z + xc1.w * xr1.w;
        p += __shfl_xor_sync(0xFFFFFFFFu, p, 4);
        p += __shfl_xor_sync(0xFFFFFFFFu, p, 2);
        p += __shfl_xor_sync(0xFFFFFFFFu, p, 1);

        if (valid) {
            float a = p * w;
            acc0.x = fmaf(a, xc0.x, acc0.x);
            acc0.y = fmaf(a, xc0.y, acc0.y);
            acc0.z = fmaf(a, xc0.z, acc0.z);
            acc0.w = fmaf(a, xc0.w, acc0.w);
            acc1.x = fmaf(a, xc1.x, acc1.x);
            acc1.y = fmaf(a, xc1.y, acc1.y);
            acc1.z = fmaf(a, xc1.z, acc1.z);
            acc1.w = fmaf(a, xc1.w, acc1.w);
        }

        // ---- rotate pipeline ----
        r_cur = r_n; c_cur = c_n; xc0 = nxc0; xc1 = nxc1;
    }

    if (any) {
        atomicAdd(&out4[seg_r * 16 + q],     acc0);
        atomicAdd(&out4[seg_r * 16 + 8 + q], acc1);
    }
}

// ---------------------------------------------------------------------------
extern "C" void kernel_launch(void* const* d_in, const int* in_sizes, int n_in,
                              void* d_out, int out_size)
{
    const float4* X4 = (const float4*)d_in[0];
    const float4* W4 = (const float4*)d_in[1];
    const float*  aw = (const float*)d_in[2];
    const int*   row = (const int*)d_in[3];
    const int*   col = (const int*)d_in[4];
    float4* out4 = (float4*)d_out;

    int n_nodes = in_sizes[0] / D;
    int n_edges = in_sizes[3];

    gemm_zero_kernel<<<(n_nodes + RPB - 1) / RPB, 256>>>(X4, W4, out4, n_nodes);

    int n_warps  = (n_edges + EPW - 1) / EPW;
    int n_blocks = (n_warps + 7) / 8;
    edge_kernel<<<n_blocks, 256>>>(row, col, aw, out4, n_edges);
}